// round 4
// baseline (speedup 1.0000x reference)
#include <cuda_runtime.h>
#include <cuda_bf16.h>

// Problem constants (fixed by the dataset)
#define N_NODES 100000
#define F_DIM   64

// Scratch: per-set (pos/neg) feature-sum accumulators + edge counts.
__device__ __align__(16) float g_sum[2][N_NODES * F_DIM];   // 2 x 25.6 MB
__device__ __align__(16) float g_cnt[2][N_NODES];           // 2 x 0.4 MB

// ---------------------------------------------------------------------------
// Kernel 1: zero the accumulators (graph replays -> must run every call).
// ---------------------------------------------------------------------------
__global__ void zero_kernel() {
    const unsigned sum4 = 2u * N_NODES * F_DIM / 4u;   // float4 count
    const unsigned cnts = 2u * N_NODES;
    unsigned i = blockIdx.x * blockDim.x + threadIdx.x;
    if (i < sum4) {
        ((float4*)g_sum)[i] = make_float4(0.f, 0.f, 0.f, 0.f);
    } else if (i < sum4 + cnts) {
        ((float*)g_cnt)[i - sum4] = 0.f;
    }
}

// ---------------------------------------------------------------------------
// Kernel 2: edge scatter. One thread per (edge, float4-chunk).
// Edge indices are INT32 (JAX default; jnp.int64 is downcast without x64).
// 16 consecutive threads cover one edge's 64 floats -> coalesced gather of
// x[src]; scalar atomicAdd (RED) into g_sum[set][dst].
// ---------------------------------------------------------------------------
__global__ void scatter_kernel(const int* __restrict__ pos_ei,
                               const int* __restrict__ neg_ei,
                               const float* __restrict__ x,
                               int E) {
    unsigned idx = blockIdx.x * blockDim.x + threadIdx.x;
    unsigned per_set = (unsigned)E * 16u;
    if (idx >= 2u * per_set) return;

    int set = (idx >= per_set) ? 1 : 0;
    unsigned r = set ? (idx - per_set) : idx;
    unsigned e = r >> 4;
    unsigned c = r & 15u;

    const int* ei = set ? neg_ei : pos_ei;
    unsigned src = (unsigned)ei[e];
    unsigned dst = (unsigned)ei[(unsigned)E + e];

    float4 v = *((const float4*)(x + src * 64u) + c);

    float* t = g_sum[set] + dst * 64u + c * 4u;
    atomicAdd(t + 0, v.x);
    atomicAdd(t + 1, v.y);
    atomicAdd(t + 2, v.z);
    atomicAdd(t + 3, v.w);

    if (c == 0) {
        atomicAdd(&g_cnt[set][dst], 1.0f);
    }
}

// ---------------------------------------------------------------------------
// Kernel 3: fused SGEMM + epilogue (pure fp32 FMA).
//   out[:, 0:64]   = mean_pos @ W_pos^T  + x @ W_pos_cc^T + b_pos
//   out[:, 64:128] = mean_neg @ W_neg^T  + x @ W_neg_cc^T + b_neg
// mean rows formed by scaling segment-sum tiles with 1/max(cnt,1) at smem
// staging. Block tile: 128 rows x 128 cols, 256 threads, 8x8 micro-tiles.
// ---------------------------------------------------------------------------
__global__ __launch_bounds__(256) void gemm_kernel(
        const float* __restrict__ x,
        const float* __restrict__ Wp,
        const float* __restrict__ Wpc,
        const float* __restrict__ bp,
        const float* __restrict__ Wn,
        const float* __restrict__ Wnc,
        const float* __restrict__ bn,
        float* __restrict__ out) {
    __shared__ float xs[16][132];   // xs[k][row]  : x tile (transposed)
    __shared__ float sp[16][132];   // mean_pos tile (pre-scaled)
    __shared__ float sn[16][132];   // mean_neg tile (pre-scaled)
    __shared__ float Wa[16][128];   // Wa[k][j] : aggregate weight, col j
    __shared__ float Wc[16][128];   // Wc[k][j] : self(cc) weight, col j

    const int tid = threadIdx.x;
    const int tc  = tid & 15;        // thread col  (x8 -> 128 cols)
    const int tr  = tid >> 4;        // thread row  (x8 -> 128 rows)
    const int row0 = blockIdx.x * 128;
    const int c0   = tc * 8;
    const bool pos_side = (tc < 8);  // cols 0..63 vs 64..127

    float acc[8][8];
    #pragma unroll
    for (int r = 0; r < 8; r++)
        #pragma unroll
        for (int c = 0; c < 8; c++) acc[r][c] = 0.f;

    for (int k0 = 0; k0 < 64; k0 += 16) {
        __syncthreads();
        // ---- stage A tiles (x, scaled sum_pos, scaled sum_neg) ----
        #pragma unroll
        for (int t = 0; t < 2; t++) {
            int i     = tid * 2 + t;       // 0..511
            int chunk = i & 3;             // float4 index within 16 k's
            int row   = i >> 2;            // 0..127
            int grow  = row0 + row;
            float4 vx = make_float4(0.f,0.f,0.f,0.f);
            float4 vp = vx, vn = vx;
            float invp = 0.f, invn = 0.f;
            if (grow < N_NODES) {
                vx = *((const float4*)(x        + grow * 64 + k0) + chunk);
                vp = *((const float4*)(g_sum[0] + grow * 64 + k0) + chunk);
                vn = *((const float4*)(g_sum[1] + grow * 64 + k0) + chunk);
                invp = 1.f / fmaxf(g_cnt[0][grow], 1.f);
                invn = 1.f / fmaxf(g_cnt[1][grow], 1.f);
            }
            int kb = chunk * 4;
            xs[kb+0][row] = vx.x; xs[kb+1][row] = vx.y;
            xs[kb+2][row] = vx.z; xs[kb+3][row] = vx.w;
            sp[kb+0][row] = vp.x * invp; sp[kb+1][row] = vp.y * invp;
            sp[kb+2][row] = vp.z * invp; sp[kb+3][row] = vp.w * invp;
            sn[kb+0][row] = vn.x * invn; sn[kb+1][row] = vn.y * invn;
            sn[kb+2][row] = vn.z * invn; sn[kb+3][row] = vn.w * invn;
        }
        // ---- stage weight tiles ----
        #pragma unroll
        for (int t = 0; t < 8; t++) {
            int i = t * 256 + tid;         // 0..2047
            int j = i & 127;               // output col
            int k = i >> 7;                // 0..15
            int jj = j & 63;
            const float* W1 = (j < 64) ? Wp  : Wn;
            const float* W2 = (j < 64) ? Wpc : Wnc;
            Wa[k][j] = W1[jj * 64 + k0 + k];
            Wc[k][j] = W2[jj * 64 + k0 + k];
        }
        __syncthreads();

        // ---- compute ----
        const float (*at)[132] = pos_side ? sp : sn;
        #pragma unroll
        for (int k = 0; k < 16; k++) {
            float a[8], xv[8], w1[8], w2[8];
            #pragma unroll
            for (int r = 0; r < 8; r++) {
                a[r]  = at[k][tr * 8 + r];
                xv[r] = xs[k][tr * 8 + r];
            }
            #pragma unroll
            for (int c = 0; c < 8; c++) {
                w1[c] = Wa[k][c0 + c];
                w2[c] = Wc[k][c0 + c];
            }
            #pragma unroll
            for (int r = 0; r < 8; r++)
                #pragma unroll
                for (int c = 0; c < 8; c++)
                    acc[r][c] += a[r] * w1[c] + xv[r] * w2[c];
        }
    }

    // ---- epilogue: bias + store ----
    float b[8];
    #pragma unroll
    for (int c = 0; c < 8; c++) {
        int j = c0 + c;
        b[c] = pos_side ? bp[j] : bn[j - 64];
    }
    #pragma unroll
    for (int r = 0; r < 8; r++) {
        int grow = row0 + tr * 8 + r;
        if (grow < N_NODES) {
            #pragma unroll
            for (int c = 0; c < 8; c++)
                out[grow * 128 + c0 + c] = acc[r][c] + b[c];
        }
    }
}

// ---------------------------------------------------------------------------
extern "C" void kernel_launch(void* const* d_in, const int* in_sizes, int n_in,
                              void* d_out, int out_size) {
    const float* x   = (const float*)d_in[0];
    const int*   pe  = (const int*)d_in[1];   // int32! (JAX downcasts int64)
    const int*   ne  = (const int*)d_in[2];
    const float* Wp  = (const float*)d_in[3];
    const float* Wpc = (const float*)d_in[4];
    const float* bp  = (const float*)d_in[5];
    const float* Wn  = (const float*)d_in[6];
    const float* Wnc = (const float*)d_in[7];
    const float* bn  = (const float*)d_in[8];
    float* out = (float*)d_out;

    int E = in_sizes[1] / 2;   // edge_index is [2, E]

    // 1) zero accumulators
    unsigned ztot = 2u * N_NODES * F_DIM / 4u + 2u * N_NODES;
    zero_kernel<<<(ztot + 255) / 256, 256>>>();

    // 2) scatter both edge sets
    unsigned stot = 2u * (unsigned)E * 16u;
    scatter_kernel<<<(stot + 255) / 256, 256>>>(pe, ne, x, E);

    // 3) fused SGEMM + mean-normalize + bias + concat
    gemm_kernel<<<(N_NODES + 127) / 128, 256>>>(x, Wp, Wpc, bp, Wn, Wnc, bn, out);
}

// round 5
// speedup vs baseline: 1.5201x; 1.5201x over previous
#include <cuda_runtime.h>
#include <cuda_bf16.h>

// Problem constants (fixed by the dataset)
#define N_NODES 100000
#define F_DIM   64

// Scratch: per-set (pos/neg) feature-sum accumulators + edge counts.
__device__ __align__(16) float g_sum[2][N_NODES * F_DIM];   // 2 x 25.6 MB
__device__ __align__(16) float g_cnt[2][N_NODES];           // 2 x 0.4 MB

// ---------------------------------------------------------------------------
// Kernel 1: zero the accumulators (graph replays -> must run every call).
// ---------------------------------------------------------------------------
__global__ void zero_kernel() {
    const unsigned sum4 = 2u * N_NODES * F_DIM / 4u;   // float4 count
    const unsigned cnts = 2u * N_NODES;
    unsigned i = blockIdx.x * blockDim.x + threadIdx.x;
    if (i < sum4) {
        ((float4*)g_sum)[i] = make_float4(0.f, 0.f, 0.f, 0.f);
    } else if (i < sum4 + cnts) {
        ((float*)g_cnt)[i - sum4] = 0.f;
    }
}

// ---------------------------------------------------------------------------
// Kernel 2: edge scatter. One thread per (edge, float4-chunk).
// Edge indices are INT32. 16 consecutive threads cover one edge's 64 floats
// -> coalesced gather of x[src]; ONE vector red.global.add.v4.f32 per thread
// (4x fewer RED lanes than scalar atomicAdd -> 4x higher atomic throughput).
// ---------------------------------------------------------------------------
__global__ void scatter_kernel(const int* __restrict__ pos_ei,
                               const int* __restrict__ neg_ei,
                               const float* __restrict__ x,
                               int E) {
    unsigned idx = blockIdx.x * blockDim.x + threadIdx.x;
    unsigned per_set = (unsigned)E * 16u;
    if (idx >= 2u * per_set) return;

    int set = (idx >= per_set) ? 1 : 0;
    unsigned r = set ? (idx - per_set) : idx;
    unsigned e = r >> 4;
    unsigned c = r & 15u;

    const int* ei = set ? neg_ei : pos_ei;
    unsigned src = (unsigned)ei[e];
    unsigned dst = (unsigned)ei[(unsigned)E + e];

    float4 v = *((const float4*)(x + src * 64u) + c);

    float4* t = (float4*)(g_sum[set] + dst * 64u) + c;
    asm volatile("red.global.add.v4.f32 [%0], {%1,%2,%3,%4};"
                 :: "l"(t), "f"(v.x), "f"(v.y), "f"(v.z), "f"(v.w)
                 : "memory");

    if (c == 0) {
        atomicAdd(&g_cnt[set][dst], 1.0f);
    }
}

// ---------------------------------------------------------------------------
// Kernel 3: fused SGEMM + epilogue (pure fp32 FMA).
//   out[:, 0:64]   = mean_pos @ W_pos^T  + x @ W_pos_cc^T + b_pos
//   out[:, 64:128] = mean_neg @ W_neg^T  + x @ W_neg_cc^T + b_neg
// mean rows formed by scaling segment-sum tiles with 1/max(cnt,1) at smem
// staging. Block tile: 128 rows x 128 cols, 256 threads, 8x8 micro-tiles.
// ---------------------------------------------------------------------------
__global__ __launch_bounds__(256) void gemm_kernel(
        const float* __restrict__ x,
        const float* __restrict__ Wp,
        const float* __restrict__ Wpc,
        const float* __restrict__ bp,
        const float* __restrict__ Wn,
        const float* __restrict__ Wnc,
        const float* __restrict__ bn,
        float* __restrict__ out) {
    __shared__ float xs[16][132];   // xs[k][row]  : x tile (transposed)
    __shared__ float sp[16][132];   // mean_pos tile (pre-scaled)
    __shared__ float sn[16][132];   // mean_neg tile (pre-scaled)
    __shared__ float Wa[16][128];   // Wa[k][j] : aggregate weight, col j
    __shared__ float Wc[16][128];   // Wc[k][j] : self(cc) weight, col j

    const int tid = threadIdx.x;
    const int tc  = tid & 15;        // thread col  (x8 -> 128 cols)
    const int tr  = tid >> 4;        // thread row  (x8 -> 128 rows)
    const int row0 = blockIdx.x * 128;
    const int c0   = tc * 8;
    const bool pos_side = (tc < 8);  // cols 0..63 vs 64..127

    float acc[8][8];
    #pragma unroll
    for (int r = 0; r < 8; r++)
        #pragma unroll
        for (int c = 0; c < 8; c++) acc[r][c] = 0.f;

    for (int k0 = 0; k0 < 64; k0 += 16) {
        __syncthreads();
        // ---- stage A tiles (x, scaled sum_pos, scaled sum_neg) ----
        #pragma unroll
        for (int t = 0; t < 2; t++) {
            int i     = tid * 2 + t;       // 0..511
            int chunk = i & 3;             // float4 index within 16 k's
            int row   = i >> 2;            // 0..127
            int grow  = row0 + row;
            float4 vx = make_float4(0.f,0.f,0.f,0.f);
            float4 vp = vx, vn = vx;
            float invp = 0.f, invn = 0.f;
            if (grow < N_NODES) {
                vx = *((const float4*)(x        + grow * 64 + k0) + chunk);
                vp = *((const float4*)(g_sum[0] + grow * 64 + k0) + chunk);
                vn = *((const float4*)(g_sum[1] + grow * 64 + k0) + chunk);
                invp = 1.f / fmaxf(g_cnt[0][grow], 1.f);
                invn = 1.f / fmaxf(g_cnt[1][grow], 1.f);
            }
            int kb = chunk * 4;
            xs[kb+0][row] = vx.x; xs[kb+1][row] = vx.y;
            xs[kb+2][row] = vx.z; xs[kb+3][row] = vx.w;
            sp[kb+0][row] = vp.x * invp; sp[kb+1][row] = vp.y * invp;
            sp[kb+2][row] = vp.z * invp; sp[kb+3][row] = vp.w * invp;
            sn[kb+0][row] = vn.x * invn; sn[kb+1][row] = vn.y * invn;
            sn[kb+2][row] = vn.z * invn; sn[kb+3][row] = vn.w * invn;
        }
        // ---- stage weight tiles ----
        #pragma unroll
        for (int t = 0; t < 8; t++) {
            int i = t * 256 + tid;         // 0..2047
            int j = i & 127;               // output col
            int k = i >> 7;                // 0..15
            int jj = j & 63;
            const float* W1 = (j < 64) ? Wp  : Wn;
            const float* W2 = (j < 64) ? Wpc : Wnc;
            Wa[k][j] = W1[jj * 64 + k0 + k];
            Wc[k][j] = W2[jj * 64 + k0 + k];
        }
        __syncthreads();

        // ---- compute ----
        const float (*at)[132] = pos_side ? sp : sn;
        #pragma unroll
        for (int k = 0; k < 16; k++) {
            float a[8], xv[8], w1[8], w2[8];
            #pragma unroll
            for (int r = 0; r < 8; r++) {
                a[r]  = at[k][tr * 8 + r];
                xv[r] = xs[k][tr * 8 + r];
            }
            #pragma unroll
            for (int c = 0; c < 8; c++) {
                w1[c] = Wa[k][c0 + c];
                w2[c] = Wc[k][c0 + c];
            }
            #pragma unroll
            for (int r = 0; r < 8; r++)
                #pragma unroll
                for (int c = 0; c < 8; c++)
                    acc[r][c] += a[r] * w1[c] + xv[r] * w2[c];
        }
    }

    // ---- epilogue: bias + store ----
    float b[8];
    #pragma unroll
    for (int c = 0; c < 8; c++) {
        int j = c0 + c;
        b[c] = pos_side ? bp[j] : bn[j - 64];
    }
    #pragma unroll
    for (int r = 0; r < 8; r++) {
        int grow = row0 + tr * 8 + r;
        if (grow < N_NODES) {
            #pragma unroll
            for (int c = 0; c < 8; c++)
                out[grow * 128 + c0 + c] = acc[r][c] + b[c];
        }
    }
}

// ---------------------------------------------------------------------------
extern "C" void kernel_launch(void* const* d_in, const int* in_sizes, int n_in,
                              void* d_out, int out_size) {
    const float* x   = (const float*)d_in[0];
    const int*   pe  = (const int*)d_in[1];   // int32! (JAX downcasts int64)
    const int*   ne  = (const int*)d_in[2];
    const float* Wp  = (const float*)d_in[3];
    const float* Wpc = (const float*)d_in[4];
    const float* bp  = (const float*)d_in[5];
    const float* Wn  = (const float*)d_in[6];
    const float* Wnc = (const float*)d_in[7];
    const float* bn  = (const float*)d_in[8];
    float* out = (float*)d_out;

    int E = in_sizes[1] / 2;   // edge_index is [2, E]

    // 1) zero accumulators
    unsigned ztot = 2u * N_NODES * F_DIM / 4u + 2u * N_NODES;
    zero_kernel<<<(ztot + 255) / 256, 256>>>();

    // 2) scatter both edge sets (vectorized REDs)
    unsigned stot = 2u * (unsigned)E * 16u;
    scatter_kernel<<<(stot + 255) / 256, 256>>>(pe, ne, x, E);

    // 3) fused SGEMM + mean-normalize + bias + concat
    gemm_kernel<<<(N_NODES + 127) / 128, 256>>>(x, Wp, Wpc, bp, Wn, Wnc, bn, out);
}